// round 15
// baseline (speedup 1.0000x reference)
#include <cuda_runtime.h>
#include <cstdint>

#define BB 16
#define VV 8
#define SS 256
#define KK 66
#define NSEQ 128                 // B*V
#define ROWS (BB*SS*SS)          // 1,048,576 argmax rows
#define RPI 8

__device__ float g_part[NSEQ];
__device__ unsigned int g_cnt;   // zero-init; self-resets each launch

__device__ __forceinline__ void ffma2(unsigned long long& d,
                                      unsigned long long a,
                                      unsigned long long b)
{
    asm("fma.rn.f32x2 %0, %1, %2, %0;" : "+l"(d) : "l"(a), "l"(b));
}

// ---------------- argmax over last dim of log_pa (B,S,S,K) ----------------
__global__ void __launch_bounds__(256) argmax_kernel(const float* __restrict__ lp,
                                                     float* __restrict__ out)
{
    const unsigned FULL = 0xffffffffu;
    const int lane  = threadIdx.x & 31;
    const int gwarp = (blockIdx.x * blockDim.x + threadIdx.x) >> 5;
    const int nwarp = (gridDim.x * blockDim.x) >> 5;

    for (int base = gwarp * RPI; base < ROWS; base += nwarp * RPI) {
        float v0[RPI], v1[RPI], v2[RPI];
#pragma unroll
        for (int r = 0; r < RPI; ++r) {
            const float* p = lp + (size_t)(base + r) * KK + lane;
            v0[r] = __ldg(p);
            v1[r] = __ldg(p + 32);
            v2[r] = (lane < 2) ? __ldg(p + 64) : -3.402823466e38f;
        }
#pragma unroll
        for (int r = 0; r < RPI; ++r) {
            float best = v0[r]; int bi = lane;
            if (v1[r] > best) { best = v1[r]; bi = lane + 32; }
            if (v2[r] > best) { best = v2[r]; bi = lane + 64; }
            unsigned kb = __float_as_uint(best);
            kb = (kb & 0x80000000u) ? ~kb : (kb | 0x80000000u);
            unsigned kmax = __reduce_max_sync(FULL, kb);
            unsigned cand = (kb == kmax) ? (unsigned)bi : 0xffffffffu;
            unsigned imin = __reduce_min_sync(FULL, cand);
            if (lane == 0) out[base + r] = (float)imin;
        }
    }
}

// ---------------- CRF per-sequence kernel ----------------
// 128 threads, (128,1) -> up to 255 regs. T2 packed exp(trans) column in regs.
// Per step: batch 17 LDS.128 of alpha, 34 fma.rn.f32x2 in 4 chains, apply
// 1-step-stale renorm scale (computed concurrently by warp 3).
__global__ void __launch_bounds__(128, 1) crf_kernel(
    const float* __restrict__ score,       // (B,S,S,K)
    const int*   __restrict__ v_label,     // (B,V)
    const int*   __restrict__ orig_l,      // (B,)
    const int*   __restrict__ role_label,  // (B,V,S)
    const float* __restrict__ start_t,     // (K,)
    const float* __restrict__ trans,       // (K,K)
    const float* __restrict__ end_t,       // (K,)
    float* __restrict__ loss_out)          // scalar
{
    extern __shared__ float sE[];          // SS*KK floats = exp(a_score)
    __shared__ __align__(16) float sA[2][72];
    __shared__ int   sTag[SS];
    __shared__ float sRed[128];
    __shared__ float sScale[2][2];         // [phase][0]=1/m, [1]=log(m)
    __shared__ int   sLast;

    const int tid = threadIdx.x;
    const int n = blockIdx.x;
    const int b = n >> 3;                   // / VV
    const int qrow = v_label[n];
    const int L = orig_l[b];                // in [S/2, S]
    const float* asc = score + ((size_t)b * SS + qrow) * SS * KK;

    // tags + alpha pad init
    for (int t = tid; t < L; t += 128) sTag[t] = role_label[(size_t)n * SS + t];
    if (tid < 6) { sA[0][66 + tid] = 0.f; sA[1][66 + tid] = 0.f; }
    __syncthreads();

    // stage E = exp(a_score) for rows < L (float4 flat copy)
    {
        const float4* s4 = (const float4*)asc;
        float4* d4 = (float4*)sE;
        const int tot4 = (L * KK + 3) >> 2;
        for (int i4 = tid; i4 < tot4; i4 += 128) {
            float4 v = __ldg(s4 + i4);
            v.x = __expf(v.x); v.y = __expf(v.y);
            v.z = __expf(v.z); v.w = __expf(v.w);
            d4[i4] = v;
        }
    }

    // numerator: emission + transition gold path
    float acc = 0.f;
    for (int t = tid; t < L; t += 128)
        acc += __ldg(asc + t * KK + sTag[t]);
    for (int t = tid + 1; t < L; t += 128)
        acc += __ldg(trans + sTag[t - 1] * KK + sTag[t]);
    sRed[tid] = acc;

    // packed exp(trans) column, loop-invariant: T2[p] = (exp(T[2p][j]), exp(T[2p+1][j]))
    unsigned long long T2[34];
    if (tid < 66) {
#pragma unroll
        for (int p = 0; p < 33; ++p) {
            float lo = __expf(__ldg(trans + (2 * p)     * KK + tid));
            float hi = __expf(__ldg(trans + (2 * p + 1) * KK + tid));
            asm("mov.b64 %0, {%1, %2};" : "=l"(T2[p]) : "f"(lo), "f"(hi));
        }
        T2[33] = 0ull;                      // rows 66,67 are padding
    } else {
#pragma unroll
        for (int p = 0; p < 34; ++p) T2[p] = 0ull;
    }

    __syncthreads();
    for (int s = 64; s > 0; s >>= 1) {      // deterministic tree reduce
        if (tid < s) sRed[tid] += sRed[tid + s];
        __syncthreads();
    }
    float numer = 0.f;
    if (tid == 0)
        numer = sRed[0] + __ldg(start_t + sTag[0]) + __ldg(end_t + sTag[L - 1]);

    // alpha0 (exp domain): A[j] = exp(start_t[j]) * E[0][j]
    if (tid < 66) sA[0][tid] = __expf(start_t[tid]) * sE[tid];
    __syncthreads();

    float* Ac = sA[0];
    float* An = sA[1];
    float Cl = 0.f;                         // only tid 0's value is used
    for (int t = 1; t < L; ++t) {
        if (tid < 66) {
            float inv = 1.f;
            if (t >= 2) {                   // scale written by warp 3 at step t-1
                const int ph = (t - 1) & 1;
                inv = sScale[ph][0];
                if (tid == 0) Cl += sScale[ph][1];
            }
            // batch ALL alpha loads into registers, then packed FMA chains
            const ulonglong2* A2 = (const ulonglong2*)Ac;
            unsigned long long q0[17], q1[17];
#pragma unroll
            for (int ii = 0; ii < 17; ++ii) { ulonglong2 v = A2[ii]; q0[ii] = v.x; q1[ii] = v.y; }
            unsigned long long ae0 = 0ull, ao0 = 0ull, ae1 = 0ull, ao1 = 0ull;
#pragma unroll
            for (int ii = 0; ii < 17; ii += 2) {
                ffma2(ae0, q0[ii], T2[2 * ii]);
                ffma2(ae1, q1[ii], T2[2 * ii + 1]);
            }
#pragma unroll
            for (int ii = 1; ii < 17; ii += 2) {
                ffma2(ao0, q0[ii], T2[2 * ii]);
                ffma2(ao1, q1[ii], T2[2 * ii + 1]);
            }
            unsigned long long c0, c1;
            asm("add.rn.f32x2 %0, %1, %2;" : "=l"(c0) : "l"(ae0), "l"(ao0));
            asm("add.rn.f32x2 %0, %1, %2;" : "=l"(c1) : "l"(ae1), "l"(ao1));
            float f0, f1, f2, f3;
            asm("mov.b64 {%0, %1}, %2;" : "=f"(f0), "=f"(f1) : "l"(c0));
            asm("mov.b64 {%0, %1}, %2;" : "=f"(f2), "=f"(f3) : "l"(c1));
            float s = (f0 + f2) + (f1 + f3);
            An[tid] = s * inv * sE[t * KK + tid];
        } else if (tid >= 96) {
            // warp 3: concurrently reduce max of Ac (= alpha_{t-1}),
            // publish to sScale[t&1] for use at step t+1.
            const int l = tid - 96;
            float m = fmaxf(Ac[l], Ac[l + 32]);
            if (l < 2) m = fmaxf(m, Ac[l + 64]);
#pragma unroll
            for (int off = 16; off > 0; off >>= 1)
                m = fmaxf(m, __shfl_xor_sync(0xffffffffu, m, off));
            if (l == 0) {
                sScale[t & 1][0] = __frcp_rn(m);
                sScale[t & 1][1] = __logf(m);
            }
        }
        __syncthreads();
        float* tmp = Ac; Ac = An; An = tmp;
    }

    // log_z = Cl + log( sum_j A[j] * exp(end_t[j]) )
    float val = 0.f;
    if (tid < 66) val = Ac[tid] * __expf(end_t[tid]);
    sRed[tid] = val;
    __syncthreads();
    for (int s = 64; s > 0; s >>= 1) {
        if (tid < s) sRed[tid] += sRed[tid + s];
        __syncthreads();
    }
    if (tid == 0) {
        float logz = Cl + __logf(sRed[0]);
        g_part[n] = numer - logz;
    }

    // last block finalizes the loss (and self-resets the counter)
    __threadfence();
    if (tid == 0) {
        unsigned done = atomicAdd(&g_cnt, 1u);
        sLast = (done == NSEQ - 1);
    }
    __syncthreads();
    if (sLast) {
        __threadfence();
        sRed[tid] = g_part[tid];
        __syncthreads();
        for (int s = 64; s > 0; s >>= 1) {
            if (tid < s) sRed[tid] += sRed[tid + s];
            __syncthreads();
        }
        if (tid == 0) {
            loss_out[0] = sRed[0] / (float)NSEQ;
            g_cnt = 0u;                      // all 128 increments already landed
            __threadfence();
        }
    }
}

extern "C" void kernel_launch(void* const* d_in, const int* in_sizes, int n_in,
                              void* d_out, int out_size)
{
    (void)in_sizes; (void)n_in; (void)out_size;
    const float* log_pa     = (const float*)d_in[0];
    const float* score      = (const float*)d_in[1];
    const int*   v_label    = (const int*)d_in[2];
    // d_in[3] = v_l (unused by reference)
    const int*   orig_l     = (const int*)d_in[4];
    const int*   role_label = (const int*)d_in[5];
    const float* start_t    = (const float*)d_in[6];
    const float* trans      = (const float*)d_in[7];
    const float* end_t      = (const float*)d_in[8];
    float* out = (float*)d_out;

    const int smem = SS * KK * (int)sizeof(float);  // 67584 B
    cudaFuncSetAttribute((const void*)crf_kernel,
                         cudaFuncAttributeMaxDynamicSharedMemorySize, smem);

    crf_kernel<<<NSEQ, 128, smem>>>(
        score, v_label, orig_l, role_label, start_t, trans, end_t, out);
    argmax_kernel<<<2048, 256>>>(log_pa, out + 1);
}

// round 16
// speedup vs baseline: 1.1660x; 1.1660x over previous
#include <cuda_runtime.h>
#include <cstdint>

#define BB 16
#define VV 8
#define SS 256
#define KK 66
#define NSEQ 128                 // B*V
#define ROWS (BB*SS*SS)          // 1,048,576 argmax rows

__device__ float g_part[NSEQ];
__device__ unsigned int g_cnt;   // zero-init; self-resets each launch

__device__ __forceinline__ void ffma2(unsigned long long& d,
                                      unsigned long long a,
                                      unsigned long long b)
{
    asm("fma.rn.f32x2 %0, %1, %2, %0;" : "+l"(d) : "l"(a), "l"(b));
}

// ---------------- argmax over last dim of log_pa (B,S,S,K) ----------------
// R14-proven: 2048x256, RPI=4, no smem, occ 81.5%, ~5.6 TB/s (~51us).
__global__ void __launch_bounds__(256) argmax_kernel(const float* __restrict__ lp,
                                                     float* __restrict__ out)
{
    const int lane  = threadIdx.x & 31;
    const int gwarp = (blockIdx.x * blockDim.x + threadIdx.x) >> 5;
    const int nwarp = (gridDim.x * blockDim.x) >> 5;

    for (int base = gwarp * 4; base < ROWS; base += nwarp * 4) {
        float best[4]; int bi[4];
#pragma unroll
        for (int r = 0; r < 4; ++r) {
            const float* p = lp + (size_t)(base + r) * KK + lane;
            float v0 = __ldg(p);
            float v1 = __ldg(p + 32);
            best[r] = v0; bi[r] = lane;
            if (v1 > best[r]) { best[r] = v1; bi[r] = lane + 32; }
            if (lane < 2) {
                float v2 = __ldg(p + 64);
                if (v2 > best[r]) { best[r] = v2; bi[r] = lane + 64; }
            }
        }
#pragma unroll
        for (int r = 0; r < 4; ++r) {
            unsigned kb = __float_as_uint(best[r]);
            kb = (kb & 0x80000000u) ? ~kb : (kb | 0x80000000u);
            unsigned kmax = __reduce_max_sync(0xffffffffu, kb);
            unsigned cand = (kb == kmax) ? (unsigned)bi[r] : 0xffffffffu;
            unsigned imin = __reduce_min_sync(0xffffffffu, cand);
            if (lane == 0) out[base + r] = (float)imin;
        }
    }
}

// ---------------- CRF per-sequence kernel ----------------
// R14 compute loop (2-chain FFMA2, batched LDS). Renorm every 4 steps,
// computed concurrently by warp 3 at t%4==2 from alpha_{t-1}, applied
// (stale-by-2, algebraically exact) by compute threads at t%4==0.
__global__ void __launch_bounds__(128, 1) crf_kernel(
    const float* __restrict__ score,       // (B,S,S,K)
    const int*   __restrict__ v_label,     // (B,V)
    const int*   __restrict__ orig_l,      // (B,)
    const int*   __restrict__ role_label,  // (B,V,S)
    const float* __restrict__ start_t,     // (K,)
    const float* __restrict__ trans,       // (K,K)
    const float* __restrict__ end_t,       // (K,)
    float* __restrict__ loss_out)          // scalar
{
    extern __shared__ float sE[];          // SS*KK floats = exp(a_score)
    __shared__ __align__(16) float sA[2][72];
    __shared__ int   sTag[SS];
    __shared__ float sRed[128];
    __shared__ float sScale[2];            // [0]=1/m, [1]=log(m)
    __shared__ int   sLast;

    const int tid = threadIdx.x;
    const int n = blockIdx.x;
    const int b = n >> 3;                   // / VV
    const int qrow = v_label[n];
    const int L = orig_l[b];                // in [S/2, S]
    const float* asc = score + ((size_t)b * SS + qrow) * SS * KK;

    // tags + alpha pad init
    for (int t = tid; t < SS; t += 128) sTag[t] = role_label[(size_t)n * SS + t];
    if (tid < 6) { sA[0][66 + tid] = 0.f; sA[1][66 + tid] = 0.f; }
    __syncthreads();

    // stage E = exp(a_score): flat float4 copy (full tile)
    {
        const float4* s4 = (const float4*)asc;
        float4* d4 = (float4*)sE;
        for (int i4 = tid; i4 < (SS * KK) / 4; i4 += 128) {
            float4 v = __ldg(s4 + i4);
            v.x = __expf(v.x); v.y = __expf(v.y);
            v.z = __expf(v.z); v.w = __expf(v.w);
            d4[i4] = v;
        }
    }

    // numerator: emission + transition gold path
    float acc = 0.f;
    for (int t = tid; t < L; t += 128)
        acc += __ldg(asc + t * KK + sTag[t]);
    for (int t = tid + 1; t < L; t += 128)
        acc += __ldg(trans + sTag[t - 1] * KK + sTag[t]);
    sRed[tid] = acc;

    // packed exp(trans) column, loop-invariant: T2[p] = (exp(T[2p][j]), exp(T[2p+1][j]))
    unsigned long long T2[34];
    if (tid < 66) {
#pragma unroll
        for (int p = 0; p < 33; ++p) {
            float lo = __expf(__ldg(trans + (2 * p)     * KK + tid));
            float hi = __expf(__ldg(trans + (2 * p + 1) * KK + tid));
            asm("mov.b64 %0, {%1, %2};" : "=l"(T2[p]) : "f"(lo), "f"(hi));
        }
        T2[33] = 0ull;                      // rows 66,67 are padding
    } else {
#pragma unroll
        for (int p = 0; p < 34; ++p) T2[p] = 0ull;
    }

    __syncthreads();
    for (int s = 64; s > 0; s >>= 1) {      // deterministic tree reduce
        if (tid < s) sRed[tid] += sRed[tid + s];
        __syncthreads();
    }
    float numer = 0.f;
    if (tid == 0)
        numer = sRed[0] + __ldg(start_t + sTag[0]) + __ldg(end_t + sTag[L - 1]);

    // alpha0 (exp domain): A[j] = exp(start_t[j]) * E[0][j]
    if (tid < 66) sA[0][tid] = __expf(start_t[tid]) * sE[tid];
    __syncthreads();

    float* Ac = sA[0];
    float* An = sA[1];
    float Cl = 0.f;                         // only tid 0's value is used
    for (int t = 1; t < L; ++t) {
        const int phase = t & 3;
        if (tid < 66) {
            float inv = 1.f;
            if (phase == 0) {               // scale published at t-2 (race-free)
                inv = sScale[0];
                if (tid == 0) Cl += sScale[1];
            }
            // batch ALL alpha loads into registers, then packed FMA chains
            const ulonglong2* A2 = (const ulonglong2*)Ac;
            unsigned long long q0[17], q1[17];
#pragma unroll
            for (int ii = 0; ii < 17; ++ii) { ulonglong2 v = A2[ii]; q0[ii] = v.x; q1[ii] = v.y; }
            unsigned long long acc0 = 0ull, acc1 = 0ull;  // packed (0.f, 0.f)
#pragma unroll
            for (int ii = 0; ii < 17; ++ii) {
                ffma2(acc0, q0[ii], T2[2 * ii]);
                ffma2(acc1, q1[ii], T2[2 * ii + 1]);
            }
            float f0, f1, f2, f3;
            asm("mov.b64 {%0, %1}, %2;" : "=f"(f0), "=f"(f1) : "l"(acc0));
            asm("mov.b64 {%0, %1}, %2;" : "=f"(f2), "=f"(f3) : "l"(acc1));
            float s = (f0 + f2) + (f1 + f3);
            An[tid] = s * inv * sE[t * KK + tid];
        } else if (tid >= 96 && phase == 2) {
            // warp 3 (concurrent, 1/4 frequency): max of Ac = alpha_{t-1},
            // published for application at step t+2.
            const int l = tid - 96;
            float m = fmaxf(Ac[l], Ac[l + 32]);
            if (l < 2) m = fmaxf(m, Ac[l + 64]);
#pragma unroll
            for (int off = 16; off > 0; off >>= 1)
                m = fmaxf(m, __shfl_xor_sync(0xffffffffu, m, off));
            if (l == 0) { sScale[0] = 1.f / m; sScale[1] = __logf(m); }
        }
        __syncthreads();
        float* tmp = Ac; Ac = An; An = tmp;
    }

    // log_z = Cl + log( sum_j A[j] * exp(end_t[j]) )
    float val = 0.f;
    if (tid < 66) val = Ac[tid] * __expf(end_t[tid]);
    sRed[tid] = val;
    __syncthreads();
    for (int s = 64; s > 0; s >>= 1) {
        if (tid < s) sRed[tid] += sRed[tid + s];
        __syncthreads();
    }
    if (tid == 0) {
        float logz = Cl + __logf(sRed[0]);
        g_part[n] = numer - logz;
    }

    // last block finalizes the loss (and self-resets the counter)
    __threadfence();
    if (tid == 0) {
        unsigned done = atomicAdd(&g_cnt, 1u);
        sLast = (done == NSEQ - 1);
    }
    __syncthreads();
    if (sLast) {
        __threadfence();
        sRed[tid] = g_part[tid];
        __syncthreads();
        for (int s = 64; s > 0; s >>= 1) {
            if (tid < s) sRed[tid] += sRed[tid + s];
            __syncthreads();
        }
        if (tid == 0) {
            loss_out[0] = sRed[0] / (float)NSEQ;
            g_cnt = 0u;                      // all 128 increments already landed
            __threadfence();
        }
    }
}

extern "C" void kernel_launch(void* const* d_in, const int* in_sizes, int n_in,
                              void* d_out, int out_size)
{
    (void)in_sizes; (void)n_in; (void)out_size;
    const float* log_pa     = (const float*)d_in[0];
    const float* score      = (const float*)d_in[1];
    const int*   v_label    = (const int*)d_in[2];
    // d_in[3] = v_l (unused by reference)
    const int*   orig_l     = (const int*)d_in[4];
    const int*   role_label = (const int*)d_in[5];
    const float* start_t    = (const float*)d_in[6];
    const float* trans      = (const float*)d_in[7];
    const float* end_t      = (const float*)d_in[8];
    float* out = (float*)d_out;

    const int smem = SS * KK * (int)sizeof(float);  // 67584 B
    cudaFuncSetAttribute((const void*)crf_kernel,
                         cudaFuncAttributeMaxDynamicSharedMemorySize, smem);

    crf_kernel<<<NSEQ, 128, smem>>>(
        score, v_label, orig_l, role_label, start_t, trans, end_t, out);
    argmax_kernel<<<2048, 256>>>(log_pa, out + 1);
}